// round 13
// baseline (speedup 1.0000x reference)
#include <cuda_runtime.h>
#include <cuda_fp16.h>
#include <cstdint>

// GRUModel: T=2048, B=64, IN=256, H=256.  hid never updates -> one big GEMM:
//   gi = x[131072,256] @ w_ih^T[256,768]   via mma.sync m16n8k16 fp16 (f32 accum)
// R13: 128-thread CTAs (tile 128m x 32h), 2 CTAs/SM -> two independent barrier
//      domains per SM to fill sync/ldsm latency bubbles. cp.async 4-stage A ring,
//      B tile resident in smem, fp16 pre-converted in gmem.

#define B_DIM 64
#define IN_DIM 256
#define H_DIM 256
#define M_DIM 131072
#define G3 768

#define BM 128                 // M rows per CTA
#define NG 96                  // gemm cols per CTA = 32 h x 3 gates
#define NHT 8                  // h-tiles (256/32)
#define KC 32                  // k per chunk
#define NCH (IN_DIM / KC)      // 8
#define NSTAGE 4

#define ASTR 80                // A stage row stride bytes (64 data + 16 pad)
#define BSTR 528               // B row stride bytes (512 data + 16 pad)
#define A_STAGE_BYTES (BM * ASTR)          // 10240
#define SB_OFF (NSTAGE * A_STAGE_BYTES)    // 40960
#define SM_TOTAL (SB_OFF + NG * BSTR)      // 91648

__device__ float  g_gh[B_DIM * G3];             // gh + b_hh (+ b_ih for r,z)
__device__ __half g_xh[(size_t)M_DIM * IN_DIM]; // x in fp16 (67 MB)
__device__ __half g_wh[NHT * NG * IN_DIM];      // w_ih fp16, pre-permuted per h-tile

// ---------------- helpers ----------------
__device__ __forceinline__ uint32_t smem_u32(const void* p) {
    uint32_t a;
    asm("{ .reg .u64 t; cvta.to.shared.u64 t, %1; cvt.u32.u64 %0, t; }" : "=r"(a) : "l"(p));
    return a;
}
__device__ __forceinline__ uint32_t f2h2(float a, float b) {
    __half2 h = __floats2half2_rn(a, b);
    return *reinterpret_cast<uint32_t*>(&h);
}
__device__ __forceinline__ void ldsm4(uint32_t& r0, uint32_t& r1, uint32_t& r2, uint32_t& r3, uint32_t a) {
    asm volatile("ldmatrix.sync.aligned.m8n8.x4.shared.b16 {%0,%1,%2,%3}, [%4];"
                 : "=r"(r0), "=r"(r1), "=r"(r2), "=r"(r3) : "r"(a));
}
__device__ __forceinline__ void mma16816(float* c, uint32_t a0, uint32_t a1, uint32_t a2, uint32_t a3,
                                         uint32_t b0, uint32_t b1) {
    asm volatile("mma.sync.aligned.m16n8k16.row.col.f32.f16.f16.f32 "
                 "{%0,%1,%2,%3}, {%4,%5,%6,%7}, {%8,%9}, {%0,%1,%2,%3};"
                 : "+f"(c[0]), "+f"(c[1]), "+f"(c[2]), "+f"(c[3])
                 : "r"(a0), "r"(a1), "r"(a2), "r"(a3), "r"(b0), "r"(b1));
}
__device__ __forceinline__ float tanh_fast(float x) {
    float y;
    asm("tanh.approx.f32 %0, %1;" : "=f"(y) : "f"(x));
    return y;
}
__device__ __forceinline__ float sig_fast(float x) {
    return fmaf(0.5f, tanh_fast(0.5f * x), 0.5f);
}
__device__ __forceinline__ int wrow_of(int c, int h0) {   // c = hg*24 + gate*8 + hl
    int hg = c / 24, rm = c % 24;
    return (rm / 8) * H_DIM + h0 + hg * 8 + (rm % 8);
}
#define CP16(dst, src) asm volatile("cp.async.cg.shared.global [%0], [%1], 16;" :: "r"(dst), "l"(src))
#define CP_COMMIT()    asm volatile("cp.async.commit_group;" ::: "memory")
#define CP_WAIT2()     asm volatile("cp.async.wait_group 2;" ::: "memory")

// ---------- pre-pass: x -> fp16 ----------
__global__ __launch_bounds__(256) void conv_x(const float* __restrict__ x) {
    size_t g = (size_t)blockIdx.x * 256 + threadIdx.x;   // 8 floats each
    const float4* p = (const float4*)(x + g * 8);
    float4 a = p[0], b = p[1];
    uint4 o = make_uint4(f2h2(a.x, a.y), f2h2(a.z, a.w), f2h2(b.x, b.y), f2h2(b.z, b.w));
    *(uint4*)(g_xh + g * 8) = o;
}

// ---------- pre-pass: w_ih -> fp16, permuted to [ht][c][k] ----------
__global__ void conv_w(const float* __restrict__ w_ih) {
    int bx = blockIdx.x;                 // 0..767 = ht*NG + c
    int ht = bx / NG, c = bx % NG;
    int row = wrow_of(c, ht * 32);
    int t = threadIdx.x;                 // 64 threads x 4 k
    float4 v = *(const float4*)(w_ih + (size_t)row * IN_DIM + t * 4);
    *(uint2*)(g_wh + (size_t)bx * IN_DIM + t * 4) = make_uint2(f2h2(v.x, v.y), f2h2(v.z, v.w));
}

// ---------- gh = hid @ w_hh^T + b_hh (+ b_ih for r,z) ----------
__global__ void gh_kernel(const float* __restrict__ hid,
                          const float* __restrict__ w_hh,
                          const float* __restrict__ b_hh,
                          const float* __restrict__ b_ih) {
    int b = blockIdx.x;
    int g = blockIdx.y * 256 + threadIdx.x;
    __shared__ float hs[H_DIM];
    hs[threadIdx.x] = hid[b * H_DIM + threadIdx.x];
    __syncthreads();
    const float4* w = (const float4*)(w_hh + (size_t)g * H_DIM);
    float s = b_hh[g] + (g < 2 * H_DIM ? b_ih[g] : 0.0f);
#pragma unroll 8
    for (int k4 = 0; k4 < H_DIM / 4; k4++) {
        float4 wv = w[k4];
        s += hs[k4 * 4 + 0] * wv.x;
        s += hs[k4 * 4 + 1] * wv.y;
        s += hs[k4 * 4 + 2] * wv.z;
        s += hs[k4 * 4 + 3] * wv.w;
    }
    g_gh[b * G3 + g] = s;
}

// ---------- main GEMM + fused gate epilogue ----------
// grid (8, 1024): bx = h-tile (32 h), by = m-tile (128 rows). 128 threads = 4 warps:
// wm = wid&1 (64 rows), wn = wid>>1 (48 cols). 2 CTAs co-resident per SM.
__global__ __launch_bounds__(128, 2)
void gru_mma(const float* __restrict__ hid,
             const float* __restrict__ b_ih,
             float* __restrict__ out) {
    extern __shared__ char smem[];
    const uint32_t sb = smem_u32(smem);
    const int tid = threadIdx.x;
    const int wid = tid >> 5, lane = tid & 31;
    const int wm = wid & 1, wn = wid >> 1;
    const int m0 = blockIdx.y * BM;
    const int ht = blockIdx.x;
    const int h0 = ht * 32;

    // ---- cp.async assignments ----
    // A stage: 128 rows x 64B; thread t: row t, 4x16B segments
    const __half* aG = g_xh + (size_t)(m0 + tid) * IN_DIM;
    const uint32_t aSo = (uint32_t)(tid * ASTR);

    // ---- ldmatrix bases ----
    const uint32_t aLd = (uint32_t)((wm * 64 + (lane & 15)) * ASTR + ((lane >> 4) & 1) * 16);
    const uint32_t bLd = (uint32_t)(SB_OFF + (wn * 48 + (lane & 7) + ((lane >> 4) & 1) * 8) * BSTR
                                    + ((lane >> 3) & 1) * 16);

    // ---- prologue: resident B copy (96 rows x 512B = 3072 x 16B) ----
    {
        const __half* wbase = g_wh + (size_t)ht * NG * IN_DIM;
#pragma unroll
        for (int i = 0; i < 24; i++) {
            int idx = i * 128 + tid;
            int row = idx >> 5, seg = idx & 31;
            CP16(sb + SB_OFF + row * BSTR + seg * 16, wbase + (size_t)row * IN_DIM + seg * 8);
        }
        CP_COMMIT();
    }
    // ---- prologue: A stages 0..2 ----
#pragma unroll
    for (int s = 0; s < NSTAGE - 1; s++) {
#pragma unroll
        for (int seg = 0; seg < 4; seg++)
            CP16(sb + s * A_STAGE_BYTES + aSo + seg * 16, aG + s * KC + seg * 8);
        CP_COMMIT();
    }
    CP_WAIT2();                 // B + A0 arrived
    __syncthreads();

    float acc[4][6][4];
#pragma unroll
    for (int mi = 0; mi < 4; mi++)
#pragma unroll
        for (int ni = 0; ni < 6; ni++)
#pragma unroll
            for (int e = 0; e < 4; e++) acc[mi][ni][e] = 0.0f;

#pragma unroll
    for (int c = 0; c < NCH; c++) {
        const uint32_t ao = (uint32_t)((c & (NSTAGE - 1)) * A_STAGE_BYTES);
        const uint32_t bk = (uint32_t)(c * 64);            // k byte offset into B rows
#pragma unroll
        for (int ks = 0; ks < 2; ks++) {
            uint32_t af[4][4], bf[3][4];
#pragma unroll
            for (int mi = 0; mi < 4; mi++)
                ldsm4(af[mi][0], af[mi][1], af[mi][2], af[mi][3],
                      sb + ao + aLd + mi * (16 * ASTR) + ks * 32);
#pragma unroll
            for (int n2 = 0; n2 < 3; n2++)
                ldsm4(bf[n2][0], bf[n2][1], bf[n2][2], bf[n2][3],
                      sb + bLd + n2 * (16 * BSTR) + bk + ks * 32);
#pragma unroll
            for (int mi = 0; mi < 4; mi++)
#pragma unroll
                for (int n2 = 0; n2 < 3; n2++) {
                    mma16816(acc[mi][n2 * 2 + 0], af[mi][0], af[mi][1], af[mi][2], af[mi][3],
                             bf[n2][0], bf[n2][1]);
                    mma16816(acc[mi][n2 * 2 + 1], af[mi][0], af[mi][1], af[mi][2], af[mi][3],
                             bf[n2][2], bf[n2][3]);
                }
        }
        if (c + NSTAGE - 1 < NCH) {
            const uint32_t so = (uint32_t)(((c + NSTAGE - 1) & (NSTAGE - 1)) * A_STAGE_BYTES);
#pragma unroll
            for (int seg = 0; seg < 4; seg++)
                CP16(sb + so + aSo + seg * 16, aG + (c + NSTAGE - 1) * KC + seg * 8);
        }
        CP_COMMIT();            // always commit (keeps wait_group accounting exact)
        if (c + 1 < NCH) {
            CP_WAIT2();         // chunk c+1 arrived
            __syncthreads();
        }
    }

    // ---- epilogue: thread owns rows (gr, gr+8) per mi; r/z/n at same h ----
    const int gr = lane >> 2, tg = lane & 3;
#pragma unroll
    for (int mi = 0; mi < 4; mi++) {
#pragma unroll
        for (int half = 0; half < 2; half++) {
            const int m = m0 + wm * 64 + mi * 16 + gr + half * 8;
            const int b = m & (B_DIM - 1);
            const float* ghb = g_gh + b * G3;
            const float* hvp = hid + b * H_DIM;
            const bool tail = (m >= M_DIM - B_DIM);
#pragma unroll
            for (int q = 0; q < 2; q++) {
                const int hb = h0 + (wn * 2 + q) * 8 + tg * 2;
                float2 o;
#pragma unroll
                for (int j = 0; j < 2; j++) {
                    const int h = hb + j;
                    const int e = half * 2 + j;
                    float r = sig_fast(acc[mi][q * 3 + 0][e] + ghb[h]);
                    float z = sig_fast(acc[mi][q * 3 + 1][e] + ghb[H_DIM + h]);
                    float n = tanh_fast(fmaf(r, ghb[2 * H_DIM + h],
                                             acc[mi][q * 3 + 2][e] + __ldg(&b_ih[2 * H_DIM + h])));
                    float hv = hvp[h];
                    float ov = n + z * (hv - n);
                    if (j) o.y = ov; else o.x = ov;
                }
                *(float2*)&out[(size_t)m * H_DIM + hb] = o;
                if (tail)
                    *(float2*)&out[(size_t)M_DIM * H_DIM + (size_t)b * H_DIM + hb] = o;
            }
        }
    }
}

extern "C" void kernel_launch(void* const* d_in, const int* in_sizes, int n_in,
                              void* d_out, int out_size) {
    const float* x    = (const float*)d_in[0];
    const float* hid  = (const float*)d_in[1];
    const float* w_ih = (const float*)d_in[2];
    const float* w_hh = (const float*)d_in[3];
    const float* b_ih = (const float*)d_in[4];
    const float* b_hh = (const float*)d_in[5];
    float* out = (float*)d_out;

    cudaFuncSetAttribute(gru_mma, cudaFuncAttributeMaxDynamicSharedMemorySize, SM_TOTAL);

    conv_x<<<(M_DIM * IN_DIM) / (256 * 8), 256>>>(x);
    conv_w<<<NHT * NG, 64>>>(w_ih);
    gh_kernel<<<dim3(B_DIM, 3), 256>>>(hid, w_hh, b_hh, b_ih);
    gru_mma<<<dim3(NHT, M_DIM / BM), 128, SM_TOTAL>>>(hid, b_ih, out);
}

// round 15
// speedup vs baseline: 1.1031x; 1.1031x over previous
#include <cuda_runtime.h>
#include <cuda_fp16.h>
#include <cstdint>

// GRUModel: T=2048, B=64, IN=256, H=256.  hid never updates -> one big GEMM:
//   gi = x[131072,256] @ w_ih^T[256,768]   via mma.sync m16n8k16 fp16 (f32 accum)
// R14: 512-thread CTA (16 warps, warp tile 32x48) -> 4 warps/SMSP for latency
//      hiding; KC=64 (4 chunks, 3-stage cp.async ring) -> half the barriers.
//      B tile resident in smem; fp16 pre-converted in gmem.

#define B_DIM 64
#define IN_DIM 256
#define H_DIM 256
#define M_DIM 131072
#define G3 768

#define BM 128                 // M rows per CTA
#define NG 192                 // gemm cols per CTA = 64 h x 3 gates
#define NHT 4                  // h-tiles
#define KC 64                  // k per chunk
#define NCH (IN_DIM / KC)      // 4
#define NSTAGE 3

#define ASTR 144               // A stage row stride bytes (128 data + 16 pad)
#define BSTR 528               // B row stride bytes (512 data + 16 pad)
#define A_STAGE_BYTES (BM * ASTR)          // 18432
#define SB_OFF (NSTAGE * A_STAGE_BYTES)    // 55296
#define SM_TOTAL (SB_OFF + NG * BSTR)      // 156672

__device__ float  g_gh[B_DIM * G3];             // gh + b_hh (+ b_ih for r,z)
__device__ __half g_xh[(size_t)M_DIM * IN_DIM]; // x in fp16 (67 MB)
__device__ __half g_wh[NHT * NG * IN_DIM];      // w_ih fp16, pre-permuted per h-tile

// ---------------- helpers ----------------
__device__ __forceinline__ uint32_t smem_u32(const void* p) {
    uint32_t a;
    asm("{ .reg .u64 t; cvta.to.shared.u64 t, %1; cvt.u32.u64 %0, t; }" : "=r"(a) : "l"(p));
    return a;
}
__device__ __forceinline__ uint32_t f2h2(float a, float b) {
    __half2 h = __floats2half2_rn(a, b);
    return *reinterpret_cast<uint32_t*>(&h);
}
__device__ __forceinline__ void ldsm4(uint32_t& r0, uint32_t& r1, uint32_t& r2, uint32_t& r3, uint32_t a) {
    asm volatile("ldmatrix.sync.aligned.m8n8.x4.shared.b16 {%0,%1,%2,%3}, [%4];"
                 : "=r"(r0), "=r"(r1), "=r"(r2), "=r"(r3) : "r"(a));
}
__device__ __forceinline__ void mma16816(float* c, uint32_t a0, uint32_t a1, uint32_t a2, uint32_t a3,
                                         uint32_t b0, uint32_t b1) {
    asm volatile("mma.sync.aligned.m16n8k16.row.col.f32.f16.f16.f32 "
                 "{%0,%1,%2,%3}, {%4,%5,%6,%7}, {%8,%9}, {%0,%1,%2,%3};"
                 : "+f"(c[0]), "+f"(c[1]), "+f"(c[2]), "+f"(c[3])
                 : "r"(a0), "r"(a1), "r"(a2), "r"(a3), "r"(b0), "r"(b1));
}
__device__ __forceinline__ float tanh_fast(float x) {
    float y;
    asm("tanh.approx.f32 %0, %1;" : "=f"(y) : "f"(x));
    return y;
}
__device__ __forceinline__ float sig_fast(float x) {
    return fmaf(0.5f, tanh_fast(0.5f * x), 0.5f);
}
__device__ __forceinline__ int wrow_of(int c, int h0) {   // c = hg*24 + gate*8 + hl
    int hg = c / 24, rm = c % 24;
    return (rm / 8) * H_DIM + h0 + hg * 8 + (rm % 8);
}
#define CP16(dst, src) asm volatile("cp.async.cg.shared.global [%0], [%1], 16;" :: "r"(dst), "l"(src))
#define CP_COMMIT()    asm volatile("cp.async.commit_group;" ::: "memory")
#define CP_WAIT1()     asm volatile("cp.async.wait_group 1;" ::: "memory")

// ---------- pre-pass: x -> fp16 ----------
__global__ __launch_bounds__(256) void conv_x(const float* __restrict__ x) {
    size_t g = (size_t)blockIdx.x * 256 + threadIdx.x;   // 8 floats each
    const float4* p = (const float4*)(x + g * 8);
    float4 a = p[0], b = p[1];
    uint4 o = make_uint4(f2h2(a.x, a.y), f2h2(a.z, a.w), f2h2(b.x, b.y), f2h2(b.z, b.w));
    *(uint4*)(g_xh + g * 8) = o;
}

// ---------- pre-pass: w_ih -> fp16, permuted to [ht][c][k] ----------
__global__ void conv_w(const float* __restrict__ w_ih) {
    int bx = blockIdx.x;                 // 0..767 = ht*NG + c
    int ht = bx / NG, c = bx % NG;
    int row = wrow_of(c, ht * 64);
    int t = threadIdx.x;                 // 64 threads x 4 k
    float4 v = *(const float4*)(w_ih + (size_t)row * IN_DIM + t * 4);
    *(uint2*)(g_wh + (size_t)bx * IN_DIM + t * 4) = make_uint2(f2h2(v.x, v.y), f2h2(v.z, v.w));
}

// ---------- gh = hid @ w_hh^T + b_hh (+ b_ih for r,z) ----------
__global__ void gh_kernel(const float* __restrict__ hid,
                          const float* __restrict__ w_hh,
                          const float* __restrict__ b_hh,
                          const float* __restrict__ b_ih) {
    int b = blockIdx.x;
    int g = blockIdx.y * 256 + threadIdx.x;
    __shared__ float hs[H_DIM];
    hs[threadIdx.x] = hid[b * H_DIM + threadIdx.x];
    __syncthreads();
    const float4* w = (const float4*)(w_hh + (size_t)g * H_DIM);
    float s = b_hh[g] + (g < 2 * H_DIM ? b_ih[g] : 0.0f);
#pragma unroll 8
    for (int k4 = 0; k4 < H_DIM / 4; k4++) {
        float4 wv = w[k4];
        s += hs[k4 * 4 + 0] * wv.x;
        s += hs[k4 * 4 + 1] * wv.y;
        s += hs[k4 * 4 + 2] * wv.z;
        s += hs[k4 * 4 + 3] * wv.w;
    }
    g_gh[b * G3 + g] = s;
}

// ---------- main GEMM + fused gate epilogue ----------
// grid (4, 1024): bx = h-tile (64 h), by = m-tile (128 rows). 512 threads = 16 warps:
// wm = wid&3 (32 rows), wn = wid>>2 (48 cols).
__global__ __launch_bounds__(512, 1)
void gru_mma(const float* __restrict__ hid,
             const float* __restrict__ b_ih,
             float* __restrict__ out) {
    extern __shared__ char smem[];
    const uint32_t sb = smem_u32(smem);
    const int tid = threadIdx.x;
    const int wid = tid >> 5, lane = tid & 31;
    const int wm = wid & 3, wn = wid >> 2;
    const int m0 = blockIdx.y * BM;
    const int ht = blockIdx.x;
    const int h0 = ht * 64;

    // ---- cp.async A assignments: 1024 16B tasks, 2 per thread ----
    // task u: row = u>>3, seg = u&7
    const int ar1 = tid >> 3, as1 = tid & 7;           // task tid
    const int ar2 = ar1 + 64, as2 = as1;               // task tid+512
    const __half* aG1 = g_xh + (size_t)(m0 + ar1) * IN_DIM + as1 * 8;
    const __half* aG2 = g_xh + (size_t)(m0 + ar2) * IN_DIM + as2 * 8;
    const uint32_t aSo1 = (uint32_t)(ar1 * ASTR + as1 * 16);
    const uint32_t aSo2 = (uint32_t)(ar2 * ASTR + as2 * 16);

    // ---- ldmatrix bases ----
    const uint32_t aLd = (uint32_t)((wm * 32 + (lane & 15)) * ASTR + ((lane >> 4) & 1) * 16);
    const uint32_t bLd = (uint32_t)(SB_OFF + (wn * 48 + (lane & 7) + ((lane >> 4) & 1) * 8) * BSTR
                                    + ((lane >> 3) & 1) * 16);

    // ---- prologue: resident B copy (192 rows x 512B = 6144 x 16B, 12/thread) ----
    {
        const __half* wbase = g_wh + (size_t)ht * NG * IN_DIM;
#pragma unroll
        for (int i = 0; i < 12; i++) {
            int idx = i * 512 + tid;
            int row = idx >> 5, seg = idx & 31;
            CP16(sb + SB_OFF + row * BSTR + seg * 16, wbase + (size_t)row * IN_DIM + seg * 8);
        }
        CP_COMMIT();
    }
    // ---- prologue: A stages 0..1 ----
#pragma unroll
    for (int s = 0; s < NSTAGE - 1; s++) {
        CP16(sb + s * A_STAGE_BYTES + aSo1, aG1 + s * KC);
        CP16(sb + s * A_STAGE_BYTES + aSo2, aG2 + s * KC);
        CP_COMMIT();
    }
    CP_WAIT1();                 // B + A0 arrived
    __syncthreads();

    float acc[2][6][4];
#pragma unroll
    for (int mi = 0; mi < 2; mi++)
#pragma unroll
        for (int ni = 0; ni < 6; ni++)
#pragma unroll
            for (int e = 0; e < 4; e++) acc[mi][ni][e] = 0.0f;

#pragma unroll
    for (int c = 0; c < NCH; c++) {
        const uint32_t ao = (uint32_t)((c % NSTAGE) * A_STAGE_BYTES);
        const uint32_t bk = (uint32_t)(c * 128);           // k byte offset into B rows
#pragma unroll
        for (int ks = 0; ks < 4; ks++) {
            uint32_t af[2][4], bf[3][4];
#pragma unroll
            for (int mi = 0; mi < 2; mi++)
                ldsm4(af[mi][0], af[mi][1], af[mi][2], af[mi][3],
                      sb + ao + aLd + mi * (16 * ASTR) + ks * 32);
#pragma unroll
            for (int n2 = 0; n2 < 3; n2++)
                ldsm4(bf[n2][0], bf[n2][1], bf[n2][2], bf[n2][3],
                      sb + bLd + n2 * (16 * BSTR) + bk + ks * 32);
#pragma unroll
            for (int mi = 0; mi < 2; mi++)
#pragma unroll
                for (int n2 = 0; n2 < 3; n2++) {
                    mma16816(acc[mi][n2 * 2 + 0], af[mi][0], af[mi][1], af[mi][2], af[mi][3],
                             bf[n2][0], bf[n2][1]);
                    mma16816(acc[mi][n2 * 2 + 1], af[mi][0], af[mi][1], af[mi][2], af[mi][3],
                             bf[n2][2], bf[n2][3]);
                }
        }
        if (c + NSTAGE - 1 < NCH) {
            const uint32_t so = (uint32_t)(((c + NSTAGE - 1) % NSTAGE) * A_STAGE_BYTES);
            CP16(sb + so + aSo1, aG1 + (c + NSTAGE - 1) * KC);
            CP16(sb + so + aSo2, aG2 + (c + NSTAGE - 1) * KC);
        }
        CP_COMMIT();            // always commit (keeps wait_group accounting exact)
        if (c + 1 < NCH) {
            CP_WAIT1();         // chunk c+1 arrived
            __syncthreads();
        }
    }

    // ---- epilogue: thread owns rows (gr, gr+8) per mi; r/z/n at same h ----
    const int gr = lane >> 2, tg = lane & 3;
    const float bin0 = __ldg(&b_ih[2 * H_DIM + h0 + (wn * 2 + 0) * 8 + tg * 2]);
    const float bin1 = __ldg(&b_ih[2 * H_DIM + h0 + (wn * 2 + 0) * 8 + tg * 2 + 1]);
    const float bin2 = __ldg(&b_ih[2 * H_DIM + h0 + (wn * 2 + 1) * 8 + tg * 2]);
    const float bin3 = __ldg(&b_ih[2 * H_DIM + h0 + (wn * 2 + 1) * 8 + tg * 2 + 1]);
#pragma unroll
    for (int mi = 0; mi < 2; mi++) {
#pragma unroll
        for (int half = 0; half < 2; half++) {
            const int m = m0 + wm * 32 + mi * 16 + gr + half * 8;
            const int b = m & (B_DIM - 1);
            const float* ghb = g_gh + b * G3;
            const float* hvp = hid + b * H_DIM;
            const bool tail = (m >= M_DIM - B_DIM);
#pragma unroll
            for (int q = 0; q < 2; q++) {
                const int hb = h0 + (wn * 2 + q) * 8 + tg * 2;
                const float binA = q ? bin2 : bin0;
                const float binB = q ? bin3 : bin1;
                float2 o;
#pragma unroll
                for (int j = 0; j < 2; j++) {
                    const int h = hb + j;
                    const int e = half * 2 + j;
                    float r = sig_fast(acc[mi][q * 3 + 0][e] + ghb[h]);
                    float z = sig_fast(acc[mi][q * 3 + 1][e] + ghb[H_DIM + h]);
                    float n = tanh_fast(fmaf(r, ghb[2 * H_DIM + h],
                                             acc[mi][q * 3 + 2][e] + (j ? binB : binA)));
                    float hv = hvp[h];
                    float ov = n + z * (hv - n);
                    if (j) o.y = ov; else o.x = ov;
                }
                *(float2*)&out[(size_t)m * H_DIM + hb] = o;
                if (tail)
                    *(float2*)&out[(size_t)M_DIM * H_DIM + (size_t)b * H_DIM + hb] = o;
            }
        }
    }
}

extern "C" void kernel_launch(void* const* d_in, const int* in_sizes, int n_in,
                              void* d_out, int out_size) {
    const float* x    = (const float*)d_in[0];
    const float* hid  = (const float*)d_in[1];
    const float* w_ih = (const float*)d_in[2];
    const float* w_hh = (const float*)d_in[3];
    const float* b_ih = (const float*)d_in[4];
    const float* b_hh = (const float*)d_in[5];
    float* out = (float*)d_out;

    cudaFuncSetAttribute(gru_mma, cudaFuncAttributeMaxDynamicSharedMemorySize, SM_TOTAL);

    conv_x<<<(M_DIM * IN_DIM) / (256 * 8), 256>>>(x);
    conv_w<<<NHT * NG, 64>>>(w_ih);
    gh_kernel<<<dim3(B_DIM, 3), 256>>>(hid, w_hh, b_hh, b_ih);
    gru_mma<<<dim3(NHT, M_DIM / BM), 512, SM_TOTAL>>>(hid, b_ih, out);
}